// round 4
// baseline (speedup 1.0000x reference)
#include <cuda_runtime.h>
#include <math.h>

// ---------------------------------------------------------------------------
// DCWTv2InferenceCache: segment-tree cover-set attention decode step.
//
//   d_in[0] v_tokens     float32 [pos, 16, 64]   (pos = in_sizes[0]/1024)
//   d_in[1] q_new        float32 [1, 16, 64]
//   d_in[2] depth_proj_w float32 [18, 64, 64]
//   d_in[3] depth_temp   float32 [18]
//   out: float32 [1, 16, 64]
//
// Graph: memset d_out, memset g_f, K1 partial (HBM stream), K2 attn
// (latency-optimized: all DRAM touches coalesced through smem).
// ---------------------------------------------------------------------------

#define TOKDIM   1024            // 16 heads * 64 dims
#define HEADS    16
#define HDIM     64
#define MAXBIG   16
#define MAXNODES 40
#define GRID_P   1216            // 152 SMs * 8 blocks (256 thr)

__device__ float g_f[(size_t)MAXBIG * 64 * TOKDIM];   // up to 4 MB

struct PartParams {
    int  nBig;
    int  a[MAXBIG];              // token offset of node
    int  C[MAXBIG];              // chunks (of 64 tokens) in node
    float inv[MAXBIG];           // 1/C
    long unitBase[MAXBIG + 1];   // prefix of C[n]*64 units
};

struct AttnParams {
    int n;                       // number of cover nodes
    float inv_n;                 // 1/n
    int depth[MAXNODES];
    int K[MAXNODES];             // min(L, 64)
    int isBig[MAXNODES];         // 1 -> g_f slot off[], 0 -> v_tokens token off[]
    int off[MAXNODES];
};

// ---- K1: balanced partial chunk sums -> red into g_f ------------------------
__global__ void __launch_bounds__(256) partial_kernel(
    const float* __restrict__ V, PartParams P, long U)
{
    const int tid = threadIdx.x;
    long u  = (long)blockIdx.x       * U / GRID_P;
    long u1 = ((long)blockIdx.x + 1) * U / GRID_P;

    while (u < u1) {
        int n = 0;
        while (u >= P.unitBase[n + 1]) n++;
        long rem = u - P.unitBase[n];
        int  k   = (int)(rem / P.C[n]);
        int  c   = (int)(rem % P.C[n]);
        long run = P.C[n] - c;
        if (run > u1 - u) run = u1 - u;

        const float4* p = (const float4*)(V + ((long)P.a[n] + (long)c * 64 + k) * TOKDIM) + tid;
        const long STR = 64L * TOKDIM / 4;    // float4 stride between chunks

        float4 a0 = {0,0,0,0}, a1 = {0,0,0,0}, a2 = {0,0,0,0}, a3 = {0,0,0,0};
        long r = 0;
        for (; r + 8 <= run; r += 8) {
            float4 x0 = p[0];
            float4 x1 = p[STR];
            float4 x2 = p[2 * STR];
            float4 x3 = p[3 * STR];
            float4 x4 = p[4 * STR];
            float4 x5 = p[5 * STR];
            float4 x6 = p[6 * STR];
            float4 x7 = p[7 * STR];
            a0.x += x0.x; a0.y += x0.y; a0.z += x0.z; a0.w += x0.w;
            a1.x += x1.x; a1.y += x1.y; a1.z += x1.z; a1.w += x1.w;
            a2.x += x2.x; a2.y += x2.y; a2.z += x2.z; a2.w += x2.w;
            a3.x += x3.x; a3.y += x3.y; a3.z += x3.z; a3.w += x3.w;
            a0.x += x4.x; a0.y += x4.y; a0.z += x4.z; a0.w += x4.w;
            a1.x += x5.x; a1.y += x5.y; a1.z += x5.z; a1.w += x5.w;
            a2.x += x6.x; a2.y += x6.y; a2.z += x6.z; a2.w += x6.w;
            a3.x += x7.x; a3.y += x7.y; a3.z += x7.z; a3.w += x7.w;
            p += 8 * STR;
        }
        for (; r < run; r++) {
            float4 x0 = p[0];
            a0.x += x0.x; a0.y += x0.y; a0.z += x0.z; a0.w += x0.w;
            p += STR;
        }
        float s = P.inv[n];
        float4 acc;
        acc.x = ((a0.x + a1.x) + (a2.x + a3.x)) * s;
        acc.y = ((a0.y + a1.y) + (a2.y + a3.y)) * s;
        acc.z = ((a0.z + a1.z) + (a2.z + a3.z)) * s;
        acc.w = ((a0.w + a1.w) + (a2.w + a3.w)) * s;

        float* o = g_f + ((long)n * 64 + k) * TOKDIM + tid * 4;
        atomicAdd(o + 0, acc.x);
        atomicAdd(o + 1, acc.y);
        atomicAdd(o + 2, acc.z);
        atomicAdd(o + 3, acc.w);

        u += run;
    }
}

// ---- K2: attention (nodes + local window), red into out ---------------------
// grid = (n_nodes + 1, 16 heads), block = 512. All DRAM reads coalesced.
__global__ void __launch_bounds__(512) attn_kernel(
    const float* __restrict__ V,
    const float* __restrict__ q,
    const float* __restrict__ W,
    const float* __restrict__ temp,
    AttnParams P, int pos, float* __restrict__ out)
{
    const int src = blockIdx.x;
    const int h   = blockIdx.y;
    const int tid = threadIdx.x;

    __shared__ float buf[128 * 65];     // node: W_sh(64x65) + f_sh(64x65); local: token tile
    __shared__ float q_sh[HDIM];
    __shared__ float s_sh[512];         // scores / exp weights
    __shared__ float red[512];
    __shared__ float qd[HDIM];
    __shared__ float s_scale, s_mx, s_sum;

    if (tid < HDIM) q_sh[tid] = q[h * HDIM + tid];

    if (src < P.n) {
        // ================= cover-set node attention =================
        const int depth = P.depth[src];
        const int K     = P.K[src];
        float* W_sh = buf;                    // [64][65] transposed
        float* f_sh = buf + 64 * 65;          // [K][65]

        const float* Wd = W + (long)depth * HDIM * HDIM;
        #pragma unroll
        for (int i = tid; i < HDIM * HDIM; i += 512) {
            int d = i >> 6, e = i & 63;
            W_sh[e * 65 + d] = Wd[i];         // coalesced load, transposed store
        }
        const float* fsrc = P.isBig[src]
            ? (g_f + (long)P.off[src] * 64 * TOKDIM)
            : (V + (long)P.off[src] * TOKDIM);
        for (int i = tid; i < K * HDIM; i += 512) {
            int k = i >> 6, d = i & 63;
            f_sh[k * 65 + d] = fsrc[(long)k * TOKDIM + h * HDIM + d];
        }
        if (tid == 0) {
            float t  = temp[depth];
            float sp = log1pf(expf(t));               // softplus
            s_scale  = 1.0f / ((sp + 1e-6f) * 8.0f);  // sqrt(64)=8
        }
        __syncthreads();

        // qd = q + q @ W^T
        if (tid < HDIM) {
            float acc = q_sh[tid];
            #pragma unroll
            for (int e = 0; e < HDIM; e++) acc += q_sh[e] * W_sh[e * 65 + tid];
            qd[tid] = acc;
        }
        __syncthreads();

        // scores
        float sc = -1e30f;
        if (tid < K) {
            float acc = 0.f;
            #pragma unroll
            for (int d = 0; d < HDIM; d++) acc += qd[d] * f_sh[tid * 65 + d];
            sc = acc * s_scale;
        }
        if (tid < 64) red[tid] = sc;
        __syncthreads();

        if (tid < 32) {
            float m = fmaxf(red[tid], red[tid + 32]);
            #pragma unroll
            for (int o = 16; o > 0; o >>= 1)
                m = fmaxf(m, __shfl_xor_sync(0xffffffff, m, o));
            if (tid == 0) s_mx = m;
        }
        __syncthreads();

        float e = (tid < K) ? expf(sc - s_mx) : 0.f;
        if (tid < 64) { s_sh[tid] = e; red[tid] = e; }
        __syncthreads();

        if (tid < 32) {
            float sm = red[tid] + red[tid + 32];
            #pragma unroll
            for (int o = 16; o > 0; o >>= 1)
                sm += __shfl_xor_sync(0xffffffff, sm, o);
            if (tid == 0) s_sum = sm;
        }
        __syncthreads();

        {
            int g = tid >> 6, d = tid & 63;
            float acc = 0.f;
            for (int k = g; k < K; k += 8) acc += s_sh[k] * f_sh[k * 65 + d];
            red[tid] = acc;
        }
        __syncthreads();
        if (tid < HDIM) {
            float o = 0.f;
            #pragma unroll
            for (int gg = 0; gg < 8; gg++) o += red[gg * 64 + tid];
            atomicAdd(out + h * HDIM + tid, (o / s_sum) * P.inv_n);
        }
    } else {
        // ================= local-window attention =================
        const int nloc = pos < 512 ? pos : 512;
        const int base = pos - nloc;

        s_sh[tid] = -1e30f;

        // scores: 128-token chunks staged through smem (coalesced loads)
        const int nch = (nloc + 127) >> 7;
        for (int cc = 0; cc < nch; cc++) {
            int t0  = cc << 7;
            int cnt = nloc - t0; if (cnt > 128) cnt = 128;
            for (int i = tid; i < cnt * 64; i += 512) {
                int k = i >> 6, d = i & 63;
                buf[k * 65 + d] = V[(long)(base + t0 + k) * TOKDIM + h * HDIM + d];
            }
            __syncthreads();
            if (tid < cnt) {
                float acc = 0.f;
                #pragma unroll
                for (int d = 0; d < HDIM; d++) acc += q_sh[d] * buf[tid * 65 + d];
                s_sh[t0 + tid] = acc * 0.125f;        // 1/sqrt(64)
            }
            __syncthreads();
        }

        // block max
        red[tid] = s_sh[tid];
        __syncthreads();
        #pragma unroll
        for (int st = 256; st >= 32; st >>= 1) {
            if (tid < st) red[tid] = fmaxf(red[tid], red[tid + st]);
            __syncthreads();
        }
        if (tid < 32) {
            float m = red[tid];
            #pragma unroll
            for (int o = 16; o > 0; o >>= 1)
                m = fmaxf(m, __shfl_xor_sync(0xffffffff, m, o));
            if (tid == 0) s_mx = m;
        }
        __syncthreads();

        float e = (tid < nloc) ? expf(s_sh[tid] - s_mx) : 0.f;
        s_sh[tid] = e;
        red[tid]  = e;
        __syncthreads();
        #pragma unroll
        for (int st = 256; st >= 32; st >>= 1) {
            if (tid < st) red[tid] += red[tid + st];
            __syncthreads();
        }
        if (tid < 32) {
            float sm = red[tid];
            #pragma unroll
            for (int o = 16; o > 0; o >>= 1)
                sm += __shfl_xor_sync(0xffffffff, sm, o);
            if (tid == 0) s_sum = sm;
        }
        __syncthreads();

        // weighted sum (coalesced; V now L2-hot)
        {
            int g = tid >> 6, d = tid & 63;
            float acc = 0.f;
            for (int k = g; k < nloc; k += 8)
                acc += s_sh[k] * V[(long)(base + k) * TOKDIM + h * HDIM + d];
            red[tid] = acc;
        }
        __syncthreads();
        if (tid < HDIM) {
            float o = 0.f;
            #pragma unroll
            for (int gg = 0; gg < 8; gg++) o += red[gg * 64 + tid];
            atomicAdd(out + h * HDIM + tid, (s_sum > 0.f) ? (o / s_sum) : 0.f);
        }
    }
}

// ---------------------------------------------------------------------------
extern "C" void kernel_launch(void* const* d_in, const int* in_sizes, int n_in,
                              void* d_out, int out_size)
{
    const float* V    = (const float*)d_in[0];
    const float* q    = (const float*)d_in[1];
    const float* W    = (const float*)d_in[2];
    const float* temp = (const float*)d_in[3];

    const int pos = in_sizes[0] / TOKDIM;

    const int  LOG_N      = 17;
    const long LEAF_START = 1L << LOG_N;
    const long MAX_LEN    = 65536;

    PartParams bp;  bp.nBig = 0;
    AttnParams ap;  ap.n = 0;

    auto addNode = [&](long idx) {
        int fl = 0; long t = idx;
        while (t > 1) { t >>= 1; fl++; }
        int depth = LOG_N - fl;
        long L = 1L << depth;
        long a = (idx << depth) - LEAF_START;
        int ni = ap.n++;
        ap.depth[ni] = depth;
        ap.K[ni] = (int)(L < 64 ? L : 64);
        if (L > 64) {
            int bi = bp.nBig++;
            bp.a[bi]   = (int)a;
            bp.C[bi]   = (int)(L / 64);
            bp.inv[bi] = 1.0f / (float)(L / 64);
            ap.isBig[ni] = 1;
            ap.off[ni]   = bi;
        } else {
            ap.isBig[ni] = 0;
            ap.off[ni]   = (int)a;
        }
    };

    long l = LEAF_START;
    long r = LEAF_START + (pos < MAX_LEN ? (long)pos : MAX_LEN);
    while (l < r) {
        if (l & 1) { addNode(l); l++; }
        if (r & 1) { r--; addNode(r); }
        l >>= 1; r >>= 1;
    }
    ap.inv_n = ap.n > 0 ? 1.0f / (float)ap.n : 0.f;

    bp.unitBase[0] = 0;
    for (int i = 0; i < bp.nBig; i++)
        bp.unitBase[i + 1] = bp.unitBase[i] + (long)bp.C[i] * 64;
    long U = bp.nBig ? bp.unitBase[bp.nBig] : 0;

    cudaMemsetAsync(d_out, 0, (size_t)out_size * sizeof(float));
    if (U > 0) {
        void* gf_ptr = nullptr;
        cudaGetSymbolAddress(&gf_ptr, g_f);
        cudaMemsetAsync(gf_ptr, 0, (size_t)bp.nBig * 64 * TOKDIM * sizeof(float));
        partial_kernel<<<GRID_P, 256>>>(V, bp, U);
    }
    attn_kernel<<<dim3(ap.n + 1, HEADS), 512>>>(V, q, W, temp, ap, pos, (float*)d_out);
}